// round 13
// baseline (speedup 1.0000x reference)
#include <cuda_runtime.h>
#include <cuda_bf16.h>
#include <math.h>
#include <stdint.h>

#define B_    256
#define T_    128
#define NIN   700
#define H_    2048

// ---------------- device scratch ----------------
// g_U is T-MAJOR: [t][b][n]  (row r = t*B_ + b)
__device__ float         g_U [(size_t)B_ * T_ * H_];
__device__ __nv_bfloat16 gA0 [(size_t)H_ * H_];         // A^T splits [n][k]
__device__ __nv_bfloat16 gA1 [(size_t)H_ * H_];
__device__ __nv_bfloat16 gA2 [(size_t)H_ * H_];
__device__ __nv_bfloat16 gS  [2][(size_t)B_ * H_];      // spike ping-pong (exact 0/1)
__device__ unsigned      gCnt[T_][4];                   // frame group barriers
__device__ unsigned      gDone[T_];                     // g_U slice progress (32/slice)

// ---------------- asm helpers (sm_80+ portable) ----------------
__device__ __forceinline__ uint32_t smem_u32(const void* p) {
    uint32_t a;
    asm("{ .reg .u64 t; cvta.to.shared.u64 t, %1; cvt.u32.u64 %0, t; }"
        : "=r"(a) : "l"(p));
    return a;
}
__device__ __forceinline__ void cpa16(uint32_t dst, const void* src) {
    asm volatile("cp.async.cg.shared.global [%0], [%1], 16;"
                 :: "r"(dst), "l"(src) : "memory");
}
__device__ __forceinline__ void cpa16_z(uint32_t dst, const void* src, bool v) {
    uint32_t sz = v ? 16u : 0u;
    asm volatile("cp.async.cg.shared.global [%0], [%1], 16, %2;"
                 :: "r"(dst), "l"(src), "r"(sz) : "memory");
}
#define CP_COMMIT() asm volatile("cp.async.commit_group;" ::: "memory")
#define CP_WAIT0()  asm volatile("cp.async.wait_group 0;" ::: "memory")
#define CP_WAIT1()  asm volatile("cp.async.wait_group 1;" ::: "memory")

__device__ __forceinline__ void ldsm4(uint32_t* r, uint32_t a) {
    asm volatile("ldmatrix.sync.aligned.m8n8.x4.shared.b16 {%0,%1,%2,%3}, [%4];"
                 : "=r"(r[0]), "=r"(r[1]), "=r"(r[2]), "=r"(r[3]) : "r"(a));
}
__device__ __forceinline__ void ldsm2(uint32_t* r, uint32_t a) {
    asm volatile("ldmatrix.sync.aligned.m8n8.x2.shared.b16 {%0,%1}, [%2];"
                 : "=r"(r[0]), "=r"(r[1]) : "r"(a));
}
__device__ __forceinline__ void mma16816(float* c, const uint32_t* a,
                                         const uint32_t* b) {
    asm volatile("mma.sync.aligned.m16n8k16.row.col.f32.bf16.bf16.f32 "
                 "{%0,%1,%2,%3}, {%4,%5,%6,%7}, {%8,%9}, {%0,%1,%2,%3};"
                 : "+f"(c[0]), "+f"(c[1]), "+f"(c[2]), "+f"(c[3])
                 : "r"(a[0]), "r"(a[1]), "r"(a[2]), "r"(a[3]),
                   "r"(b[0]), "r"(b[1]));
}

// ---------------- bf16 3-way exact split ----------------
__device__ __forceinline__ void split3(float v, __nv_bfloat16& b0,
                                       __nv_bfloat16& b1, __nv_bfloat16& b2) {
    b0 = __float2bfloat16(v);
    float f0 = __bfloat162float(b0);
    b1 = __float2bfloat16(v - f0);
    float f1 = __bfloat162float(b1);
    b2 = __float2bfloat16(v - f0 - f1);
}

__device__ void split_cta_body(int sb, const float* __restrict__ A, char* smraw)
{
    float (*tile)[33] = (float(*)[33])smraw;
    const int tid = threadIdx.x;
    const int tx = tid & 31, ty = tid >> 5;
    const int gx = sb & 63, gy = sb >> 6;
    const int kbase = gy * 32, nbase = gx * 32;
    #pragma unroll
    for (int i = 0; i < 32; i += 8)
        tile[ty + i][tx] = A[(size_t)(kbase + ty + i) * H_ + nbase + tx];
    __syncthreads();
    #pragma unroll
    for (int i = 0; i < 32; i += 8) {
        float v = tile[tx][ty + i];
        size_t o = (size_t)(nbase + ty + i) * H_ + kbase + tx;
        __nv_bfloat16 b0, b1, b2; split3(v, b0, b1, b2);
        gA0[o] = b0; gA1[o] = b1; gA2[o] = b2;
    }
}

// ---- one input-GEMM tile (fp32, BK=16, FP order bit-identical to R9) ------
// Writes g_U rows [mt*128,(mt+1)*128) (t-major), cols [nt*128,(nt+1)*128).
__device__ void gemm_tile_body(int mt, int nt,
                               const float* __restrict__ X,
                               const float* __restrict__ W,
                               const float* __restrict__ bias, char* smraw)
{
    constexpr int BK = 16, TM = 8, TN = 8;
    float (*As)[128][BK] = (float(*)[128][BK])smraw;            // 2 x 8KB
    float (*Bs)[BK][128] = (float(*)[BK][128])(smraw + 16384);  // 2 x 8KB

    const int tid = threadIdx.x;
    const int tRow = (tid >> 4) << 3, tCol = (tid & 15) << 3;
    const int m0g = mt * 128, n0g = nt * 128;

    auto xrow = [&](int r) -> const float* {
        int rr = m0g + r;                 // t-major row: rr = t*256 + b
        int b = rr & (B_ - 1), t = rr >> 8;
        return X + ((size_t)b * T_ + t) * NIN;
    };
    auto load_stage = [&](int buf, int k0) {
        #pragma unroll
        for (int h = 0; h < 2; h++) {
            int c = tid + h * 256;
            int ar = c >> 2, aj = (c & 3) * 4;
            cpa16_z(smem_u32(&As[buf][ar][aj]), xrow(ar) + k0 + aj,
                    (k0 + aj) < NIN);
            int brw = c >> 5, bc = (c & 31) * 4;
            cpa16_z(smem_u32(&Bs[buf][brw][bc]),
                    W + (size_t)(k0 + brw) * H_ + n0g + bc, (k0 + brw) < NIN);
        }
    };

    float acc[TM][TN];
    #pragma unroll
    for (int i = 0; i < TM; i++)
        #pragma unroll
        for (int j = 0; j < TN; j++) acc[i][j] = 0.f;

    constexpr int NS = (NIN + BK - 1) / BK;   // 44
    load_stage(0, 0); CP_COMMIT();

    for (int s = 0; s < NS; s++) {
        int buf = s & 1;
        __syncthreads();
        if (s + 1 < NS) { load_stage(buf ^ 1, (s + 1) * BK); CP_COMMIT(); CP_WAIT1(); }
        else CP_WAIT0();
        __syncthreads();

        #pragma unroll
        for (int k = 0; k < BK; k++) {
            float aF[TM], bF[TN];
            #pragma unroll
            for (int i = 0; i < TM; i++) aF[i] = As[buf][tRow + i][k];
            float4 b0 = *(const float4*)&Bs[buf][k][tCol];
            float4 b1 = *(const float4*)&Bs[buf][k][tCol + 4];
            bF[0] = b0.x; bF[1] = b0.y; bF[2] = b0.z; bF[3] = b0.w;
            bF[4] = b1.x; bF[5] = b1.y; bF[6] = b1.z; bF[7] = b1.w;
            #pragma unroll
            for (int i = 0; i < TM; i++)
                #pragma unroll
                for (int j = 0; j < TN; j++) acc[i][j] += aF[i] * bF[j];
        }
    }

    const int n0 = n0g + tCol;
    #pragma unroll
    for (int i = 0; i < TM; i++) {
        size_t row = (size_t)(m0g + tRow + i) * H_;
        #pragma unroll
        for (int j = 0; j < TN; j++)
            __stcs(&g_U[row + n0 + j], 0.5f * (acc[i][j] + bias[n0 + j]));
    }
}

// ---------------- pre: g_U slices t in {0,1} + A splits ----------------
__global__ void __launch_bounds__(256)
k_pre(const float* __restrict__ X, const float* __restrict__ W,
      const float* __restrict__ A, const float* __restrict__ bias)
{
    __shared__ __align__(16) char smraw[33024];
    int bx = blockIdx.x;
    if (bx < 64) gemm_tile_body(bx >> 4, bx & 15, X, W, bias, smraw);
    else         split_cta_body(bx - 64, A, smraw);
}

// ---------------- frame 0 (spike0 = 0 -> r = 0) ----------------
__global__ void k_frame0(const float* __restrict__ mem_init,
                         float* __restrict__ out_mems,
                         float* __restrict__ out_spikes)
{
    size_t idx = (size_t)blockIdx.x * 256 + threadIdx.x;
    int b = (int)(idx / H_), n = (int)(idx % H_);
    size_t o = ((size_t)b * T_) * H_ + n;
    float u = g_U[(size_t)b * H_ + n];        // t=0 slice, t-major
    float y = tanhf(u);
    float mem = mem_init[idx] * 0.5f - 0.5f * (1.0f - 0.0f) + y;
    float sp = (mem > 0.5f) ? 1.0f : 0.0f;
    out_mems[o] = mem;
    out_spikes[o] = sp;
    gS[0][idx] = __float2bfloat16(sp);
}

// ==== mega kernel: 128 persistent frame CTAs + 4032 co-resident GEMM CTAs ==
#define SPD2 72
#define TSZ  (64 * SPD2)
#define STG  (4 * TSZ)
#define FR_SMEM_B (3 * STG * 2)          // 110592 B

__device__ void frames_body(float* __restrict__ out_mems,
                            float* __restrict__ out_spikes,
                            __nv_bfloat16* smf)
{
    const int tid = threadIdx.x;
    const int lane = tid & 31, w = tid >> 5;
    const int wm = w & 1, wn = w >> 1;
    const int l15 = lane & 15;
    const int bn = blockIdx.x & 31, bm = blockIdx.x >> 5;
    const int n0 = bn * 64, m0 = bm * 64;

    const __nv_bfloat16* Ap[3] = { gA0 + (size_t)n0 * H_,
                                   gA1 + (size_t)n0 * H_,
                                   gA2 + (size_t)n0 * H_ };

    const int gq = lane >> 2, tq = lane & 3;
    int eb[2][2], en[2][2];
    #pragma unroll
    for (int mi = 0; mi < 2; mi++)
        #pragma unroll
        for (int h = 0; h < 2; h++)
            eb[mi][h] = m0 + wm * 32 + mi * 16 + gq + h * 8;
    #pragma unroll
    for (int ni = 0; ni < 2; ni++)
        #pragma unroll
        for (int e = 0; e < 2; e++)
            en[ni][e] = n0 + wn * 16 + ni * 8 + tq * 2 + e;

    float memc[2][2][2][2];
    #pragma unroll
    for (int mi = 0; mi < 2; mi++)
        #pragma unroll
        for (int ni = 0; ni < 2; ni++)
            #pragma unroll
            for (int h = 0; h < 2; h++)
                #pragma unroll
                for (int e = 0; e < 2; e++)
                    memc[mi][ni][h][e] =
                        out_mems[((size_t)eb[mi][h] * T_) * H_ + en[ni][e]];

    const int a_row = wm * 32 + l15;
    const int b_rb  = wn * 16 + (l15 & 7);
    const int a_co  = (lane >> 4) * 8;
    const int b_co  = ((l15 >> 3) & 1) * 8;

    for (int t = 1; t < T_; t++) {
        if (t >= 2) {
            if (tid == 0) {
                while (atomicAdd(&gDone[t], 0u) < 32u) __nanosleep(64);
                while (atomicAdd(&gCnt[t - 1][bm], 0u) < 32u) __nanosleep(64);
            }
            __syncthreads();
        }

        const __nv_bfloat16* Sg = gS[(t + 1) & 1];

        auto load_stage = [&](int buf, int k0) {
            __nv_bfloat16* st = smf + (size_t)buf * STG;
            #pragma unroll
            for (int i = 0; i < 8; i++) {
                int c = tid + i * 256;
                int tile = c >> 9;
                int r = (c >> 3) & 63;
                int j = (c & 7) * 8;
                const __nv_bfloat16* src = (tile == 0)
                    ? Sg + (size_t)(m0 + r) * H_ + k0 + j
                    : Ap[tile - 1] + (size_t)r * H_ + k0 + j;
                cpa16(smem_u32(st + tile * TSZ + r * SPD2 + j), src);
            }
        };

        float master[2][2][4];
        #pragma unroll
        for (int a = 0; a < 2; a++)
            #pragma unroll
            for (int b = 0; b < 2; b++)
                #pragma unroll
                for (int c = 0; c < 4; c++) master[a][b][c] = 0.f;

        load_stage(0, 0);  CP_COMMIT();
        load_stage(1, 64); CP_COMMIT();

        constexpr int NS = H_ / 64;
        for (int s = 0; s < NS; s++) {
            int buf = s % 3;
            CP_WAIT1();
            __syncthreads();
            if (s + 2 < NS) load_stage((s + 2) % 3, (s + 2) * 64);
            CP_COMMIT();

            uint32_t sb = smem_u32(smf + (size_t)buf * STG);
            #pragma unroll
            for (int c32 = 0; c32 < 2; c32++) {
                const uint32_t kbyte = (uint32_t)c32 * 64;

                float tacc[2][2][4];
                #pragma unroll
                for (int a = 0; a < 2; a++)
                    #pragma unroll
                    for (int b = 0; b < 2; b++)
                        #pragma unroll
                        for (int c = 0; c < 4; c++) tacc[a][b][c] = 0.f;

                #pragma unroll
                for (int kk = 0; kk < 2; kk++) {
                    uint32_t af[2][4];
                    #pragma unroll
                    for (int mi = 0; mi < 2; mi++) {
                        int row = a_row + mi * 16;
                        ldsm4(af[mi], sb + (uint32_t)((row * SPD2 + a_co) * 2
                                                      + kbyte + kk * 32));
                    }
                    #pragma unroll
                    for (int p = 0; p < 3; p++) {
                        uint32_t ab = sb + (uint32_t)((1 + p) * TSZ * 2);
                        #pragma unroll
                        for (int ni = 0; ni < 2; ni++) {
                            uint32_t bfr[2];
                            int row = b_rb + ni * 8;
                            ldsm2(bfr, ab + (uint32_t)((row * SPD2 + b_co) * 2
                                                       + kbyte + kk * 32));
                            mma16816(tacc[0][ni], af[0], bfr);
                            mma16816(tacc[1][ni], af[1], bfr);
                        }
                    }
                }
                #pragma unroll
                for (int a = 0; a < 2; a++)
                    #pragma unroll
                    for (int b = 0; b < 2; b++)
                        #pragma unroll
                        for (int c = 0; c < 4; c++)
                            master[a][b][c] += tacc[a][b][c];
            }
        }

        __nv_bfloat16* Sout = gS[t & 1];
        #pragma unroll
        for (int mi = 0; mi < 2; mi++)
            #pragma unroll
            for (int ni = 0; ni < 2; ni++)
                #pragma unroll
                for (int h = 0; h < 2; h++)
                    #pragma unroll
                    for (int e = 0; e < 2; e++) {
                        int b = eb[mi][h];
                        int n = en[ni][e];
                        size_t o = ((size_t)b * T_ + t) * H_ + n;
                        float u = __ldcs(&g_U[((size_t)t * B_ + b) * H_ + n]);
                        float mem_prev = memc[mi][ni][h][e];
                        float sp_prev = (mem_prev > 0.5f) ? 1.0f : 0.0f;
                        float y = tanhf(0.5f * master[mi][ni][h * 2 + e] + u);
                        float mem = mem_prev * 0.5f - 0.5f * (1.0f - sp_prev) + y;
                        float sp = (mem > 0.5f) ? 1.0f : 0.0f;
                        __stcs(&out_mems[o], mem);
                        __stcs(&out_spikes[o], sp);
                        Sout[(size_t)b * H_ + n] = __float2bfloat16(sp);
                        memc[mi][ni][h][e] = mem;
                    }

        __threadfence();
        __syncthreads();
        if (tid == 0 && t < T_ - 1) atomicAdd(&gCnt[t][bm], 1u);
    }
}

__global__ void __launch_bounds__(256, 2)
k_main(const float* __restrict__ X, const float* __restrict__ W,
       const float* __restrict__ bias,
       float* __restrict__ out_mems, float* __restrict__ out_spikes)
{
    extern __shared__ __align__(16) char smraw[];
    int bx = blockIdx.x;
    if (bx < 128) {
        frames_body(out_mems, out_spikes, (__nv_bfloat16*)smraw);
    } else {
        int tile = 64 + (bx - 128);       // tiles for t >= 2, ascending t
        int mt = tile >> 4, nt = tile & 15;
        gemm_tile_body(mt, nt, X, W, bias, smraw);
        __threadfence();
        __syncthreads();
        if (threadIdx.x == 0) atomicAdd(&gDone[mt >> 1], 1u);
    }
}

// ----------------------------------------------------------------------------
extern "C" void kernel_launch(void* const* d_in, const int* in_sizes, int n_in,
                              void* d_out, int out_size)
{
    const float* x        = (const float*)d_in[0];
    const float* W_in     = (const float*)d_in[1];
    const float* Arec     = (const float*)d_in[2];
    const float* bias     = (const float*)d_in[3];
    const float* mem_init = (const float*)d_in[4];

    float* out        = (float*)d_out;
    float* out_mems   = out;
    float* out_spikes = out + (size_t)B_ * T_ * H_;

    cudaFuncSetAttribute(k_main,
                         cudaFuncAttributeMaxDynamicSharedMemorySize, FR_SMEM_B);

    void* p = nullptr;
    cudaGetSymbolAddress(&p, gCnt);
    cudaMemsetAsync(p, 0, sizeof(unsigned) * T_ * 4);
    cudaGetSymbolAddress(&p, gDone);
    cudaMemsetAsync(p, 0, sizeof(unsigned) * T_);

    k_pre<<<64 + 4096, 256>>>(x, W_in, Arec, bias);
    k_frame0<<<(B_ * H_) / 256, 256>>>(mem_init, out_mems, out_spikes);

    k_main<<<128 + 4032, 256, FR_SMEM_B>>>(x, W_in, bias,
                                           out_mems, out_spikes);
}

// round 14
// speedup vs baseline: 1.2705x; 1.2705x over previous
#include <cuda_runtime.h>
#include <cuda_bf16.h>
#include <math.h>
#include <stdint.h>

#define B_    256
#define T_    128
#define NIN   700
#define H_    2048

// ---------------- device scratch ----------------
__device__ float         g_U [(size_t)B_ * T_ * H_];    // 0.5*(x@W+bias), b-major
__device__ __nv_bfloat16 gA0 [(size_t)H_ * H_];         // A^T splits [n][k]
__device__ __nv_bfloat16 gA1 [(size_t)H_ * H_];
__device__ __nv_bfloat16 gA2 [(size_t)H_ * H_];
__device__ __nv_bfloat16 gS  [2][(size_t)B_ * H_];      // spike ping-pong (exact 0/1)
__device__ unsigned      gCnt[T_][4];                   // group barrier counters

// ---------------- asm helpers (sm_80+ portable) ----------------
__device__ __forceinline__ uint32_t smem_u32(const void* p) {
    uint32_t a;
    asm("{ .reg .u64 t; cvta.to.shared.u64 t, %1; cvt.u32.u64 %0, t; }"
        : "=r"(a) : "l"(p));
    return a;
}
__device__ __forceinline__ void cpa16(uint32_t dst, const void* src) {
    asm volatile("cp.async.cg.shared.global [%0], [%1], 16;"
                 :: "r"(dst), "l"(src) : "memory");
}
__device__ __forceinline__ void cpa16_z(uint32_t dst, const void* src, bool v) {
    uint32_t sz = v ? 16u : 0u;
    asm volatile("cp.async.cg.shared.global [%0], [%1], 16, %2;"
                 :: "r"(dst), "l"(src), "r"(sz) : "memory");
}
#define CP_COMMIT() asm volatile("cp.async.commit_group;" ::: "memory")
#define CP_WAIT0()  asm volatile("cp.async.wait_group 0;" ::: "memory")
#define CP_WAIT1()  asm volatile("cp.async.wait_group 1;" ::: "memory")

__device__ __forceinline__ void ldsm4(uint32_t* r, uint32_t a) {
    asm volatile("ldmatrix.sync.aligned.m8n8.x4.shared.b16 {%0,%1,%2,%3}, [%4];"
                 : "=r"(r[0]), "=r"(r[1]), "=r"(r[2]), "=r"(r[3]) : "r"(a));
}
__device__ __forceinline__ void ldsm2(uint32_t* r, uint32_t a) {
    asm volatile("ldmatrix.sync.aligned.m8n8.x2.shared.b16 {%0,%1}, [%2];"
                 : "=r"(r[0]), "=r"(r[1]) : "r"(a));
}
__device__ __forceinline__ void mma16816(float* c, const uint32_t* a,
                                         const uint32_t* b) {
    asm volatile("mma.sync.aligned.m16n8k16.row.col.f32.bf16.bf16.f32 "
                 "{%0,%1,%2,%3}, {%4,%5,%6,%7}, {%8,%9}, {%0,%1,%2,%3};"
                 : "+f"(c[0]), "+f"(c[1]), "+f"(c[2]), "+f"(c[3])
                 : "r"(a[0]), "r"(a[1]), "r"(a[2]), "r"(a[3]),
                   "r"(b[0]), "r"(b[1]));
}
// packed 2-lane IEEE fp32 FMA (Blackwell f32x2; each lane = fma.rn.f32)
__device__ __forceinline__ void ffma2(uint64_t& acc, uint64_t a, uint64_t b) {
    asm("fma.rn.f32x2 %0, %1, %2, %0;" : "+l"(acc) : "l"(a), "l"(b));
}
__device__ __forceinline__ uint64_t pack2(float lo, float hi) {
    uint64_t r;
    asm("mov.b64 %0, {%1, %2};" : "=l"(r) : "f"(lo), "f"(hi));
    return r;
}
__device__ __forceinline__ void unpack2(uint64_t v, float& lo, float& hi) {
    asm("mov.b64 {%0, %1}, %2;" : "=f"(lo), "=f"(hi) : "l"(v));
}

// ---------------- bf16 3-way exact split ----------------
__device__ __forceinline__ void split3(float v, __nv_bfloat16& b0,
                                       __nv_bfloat16& b1, __nv_bfloat16& b2) {
    b0 = __float2bfloat16(v);
    float f0 = __bfloat162float(b0);
    b1 = __float2bfloat16(v - f0);
    float f1 = __bfloat162float(b1);
    b2 = __float2bfloat16(v - f0 - f1);
}

__global__ void k_split_A(const float* __restrict__ A) {
    __shared__ float tile[32][33];
    int tx = threadIdx.x, ty = threadIdx.y;
    int kbase = blockIdx.y * 32, nbase = blockIdx.x * 32;
    #pragma unroll
    for (int i = 0; i < 32; i += 8)
        tile[ty + i][tx] = A[(size_t)(kbase + ty + i) * H_ + nbase + tx];
    __syncthreads();
    #pragma unroll
    for (int i = 0; i < 32; i += 8) {
        float v = tile[tx][ty + i];
        size_t o = (size_t)(nbase + ty + i) * H_ + kbase + tx;
        __nv_bfloat16 b0, b1, b2; split3(v, b0, b1, b2);
        gA0[o] = b0; gA1[o] = b1; gA2[o] = b2;
    }
}

// ------- input GEMM: fp32, ascending-k per-element order (bit-identical) ---
// Inner loop uses packed fma.rn.f32x2: output pair (j, j+1) per instruction.
// Each lane is an IEEE RN fp32 FMA -> per-element FP sequence unchanged.
__global__ void __launch_bounds__(256) k_input_gemm(
    const float* __restrict__ X, const float* __restrict__ W,
    const float* __restrict__ bias)
{
    constexpr int K = NIN, N = H_;
    constexpr int BM = 128, BN = 128, BK = 16, TM = 8, TN = 8;
    __shared__ __align__(16) float As[2][BM][BK];
    __shared__ __align__(16) float Bs[2][BK][BN];

    const int tid = threadIdx.x;
    const int bm = blockIdx.y, bn = blockIdx.x;
    const int tRow = (tid >> 4) << 3, tCol = (tid & 15) << 3;
    const int m0g = bm * BM, n0g = bn * BN;

    auto load_stage = [&](int buf, int k0) {
        #pragma unroll
        for (int h = 0; h < 2; h++) {
            int c = tid + h * 256;
            int ar = c >> 2, aj = (c & 3) * 4;
            cpa16_z(smem_u32(&As[buf][ar][aj]),
                    X + (size_t)(m0g + ar) * K + k0 + aj, (k0 + aj) < K);
            int brw = c >> 5, bc = (c & 31) * 4;
            cpa16_z(smem_u32(&Bs[buf][brw][bc]),
                    W + (size_t)(k0 + brw) * N + n0g + bc, (k0 + brw) < K);
        }
    };

    uint64_t accP[TM][TN / 2];
    #pragma unroll
    for (int i = 0; i < TM; i++)
        #pragma unroll
        for (int j = 0; j < TN / 2; j++) accP[i][j] = pack2(0.f, 0.f);

    constexpr int NS = (K + BK - 1) / BK;   // 44
    load_stage(0, 0); CP_COMMIT();

    for (int s = 0; s < NS; s++) {
        int buf = s & 1;
        __syncthreads();
        if (s + 1 < NS) { load_stage(buf ^ 1, (s + 1) * BK); CP_COMMIT(); CP_WAIT1(); }
        else CP_WAIT0();
        __syncthreads();

        #pragma unroll
        for (int k = 0; k < BK; k++) {
            uint64_t aP[TM];
            #pragma unroll
            for (int i = 0; i < TM; i++) {
                float a = As[buf][tRow + i][k];
                aP[i] = pack2(a, a);
            }
            float4 b0 = *(const float4*)&Bs[buf][k][tCol];
            float4 b1 = *(const float4*)&Bs[buf][k][tCol + 4];
            uint64_t bP[TN / 2];
            bP[0] = pack2(b0.x, b0.y);
            bP[1] = pack2(b0.z, b0.w);
            bP[2] = pack2(b1.x, b1.y);
            bP[3] = pack2(b1.z, b1.w);
            #pragma unroll
            for (int i = 0; i < TM; i++)
                #pragma unroll
                for (int j = 0; j < TN / 2; j++)
                    ffma2(accP[i][j], aP[i], bP[j]);
        }
    }

    const int m0 = m0g + tRow, n0 = n0g + tCol;
    #pragma unroll
    for (int i = 0; i < TM; i++) {
        size_t row = (size_t)(m0 + i) * N;
        #pragma unroll
        for (int j = 0; j < TN / 2; j++) {
            float lo, hi;
            unpack2(accP[i][j], lo, hi);
            g_U[row + n0 + 2 * j + 0] = 0.5f * (lo + bias[n0 + 2 * j + 0]);
            g_U[row + n0 + 2 * j + 1] = 0.5f * (hi + bias[n0 + 2 * j + 1]);
        }
    }
}

// ---------------- frame 0 (spike0 = 0 -> r = 0) ----------------
__global__ void k_frame0(const float* __restrict__ mem_init,
                         float* __restrict__ out_mems,
                         float* __restrict__ out_spikes)
{
    size_t idx = (size_t)blockIdx.x * 256 + threadIdx.x;
    int b = (int)(idx / H_), n = (int)(idx % H_);
    size_t o = ((size_t)b * T_) * H_ + n;
    float u = g_U[o];
    float y = tanhf(u);
    float mem = mem_init[idx] * 0.5f - 0.5f * (1.0f - 0.0f) + y;
    float sp = (mem > 0.5f) ? 1.0f : 0.0f;
    out_mems[o] = mem;
    out_spikes[o] = sp;
    gS[0][idx] = __float2bfloat16(sp);
}

// ==== persistent frames kernel (verbatim round 12) ==========================
#define SPD2 72
#define TSZ  (64 * SPD2)
#define STG  (4 * TSZ)
#define FR_SMEM_B (3 * STG * 2)          // 110592 B

__global__ void __launch_bounds__(256)
k_frames(float* __restrict__ out_mems, float* __restrict__ out_spikes)
{
    extern __shared__ __align__(16) __nv_bfloat16 smf[];
    const int tid = threadIdx.x;
    const int lane = tid & 31, w = tid >> 5;
    const int wm = w & 1, wn = w >> 1;               // warp tile 32(m) x 16(n)
    const int l15 = lane & 15;
    const int n0 = blockIdx.x * 64, m0 = blockIdx.y * 64;
    const int bm = blockIdx.y;

    const __nv_bfloat16* Ap[3] = { gA0 + (size_t)n0 * H_,
                                   gA1 + (size_t)n0 * H_,
                                   gA2 + (size_t)n0 * H_ };

    const int gq = lane >> 2, tq = lane & 3;
    int eb[2][2], en[2][2];
    #pragma unroll
    for (int mi = 0; mi < 2; mi++)
        #pragma unroll
        for (int h = 0; h < 2; h++)
            eb[mi][h] = m0 + wm * 32 + mi * 16 + gq + h * 8;
    #pragma unroll
    for (int ni = 0; ni < 2; ni++)
        #pragma unroll
        for (int e = 0; e < 2; e++)
            en[ni][e] = n0 + wn * 16 + ni * 8 + tq * 2 + e;

    float memc[2][2][2][2];
    #pragma unroll
    for (int mi = 0; mi < 2; mi++)
        #pragma unroll
        for (int ni = 0; ni < 2; ni++)
            #pragma unroll
            for (int h = 0; h < 2; h++)
                #pragma unroll
                for (int e = 0; e < 2; e++)
                    memc[mi][ni][h][e] =
                        out_mems[((size_t)eb[mi][h] * T_) * H_ + en[ni][e]];

    const int a_row = wm * 32 + l15;
    const int b_rb  = wn * 16 + (l15 & 7);
    const int a_co  = (lane >> 4) * 8;
    const int b_co  = ((l15 >> 3) & 1) * 8;

    for (int t = 1; t < T_; t++) {
        if (t >= 2) {
            if (tid == 0)
                while (atomicAdd(&gCnt[t - 1][bm], 0u) < 32u) __nanosleep(64);
            __syncthreads();
        }

        const __nv_bfloat16* Sg = gS[(t + 1) & 1];

        auto load_stage = [&](int buf, int k0) {
            __nv_bfloat16* st = smf + (size_t)buf * STG;
            #pragma unroll
            for (int i = 0; i < 8; i++) {
                int c = tid + i * 256;
                int tile = c >> 9;
                int r = (c >> 3) & 63;
                int j = (c & 7) * 8;
                const __nv_bfloat16* src = (tile == 0)
                    ? Sg + (size_t)(m0 + r) * H_ + k0 + j
                    : Ap[tile - 1] + (size_t)r * H_ + k0 + j;
                cpa16(smem_u32(st + tile * TSZ + r * SPD2 + j), src);
            }
        };

        float master[2][2][4];
        #pragma unroll
        for (int a = 0; a < 2; a++)
            #pragma unroll
            for (int b = 0; b < 2; b++)
                #pragma unroll
                for (int c = 0; c < 4; c++) master[a][b][c] = 0.f;

        load_stage(0, 0);  CP_COMMIT();
        load_stage(1, 64); CP_COMMIT();

        constexpr int NS = H_ / 64;     // 32 stages, BK=64 (2 x BK=32 chunks)
        for (int s = 0; s < NS; s++) {
            int buf = s % 3;
            CP_WAIT1();
            __syncthreads();
            if (s + 2 < NS) load_stage((s + 2) % 3, (s + 2) * 64);
            CP_COMMIT();

            uint32_t sb = smem_u32(smf + (size_t)buf * STG);
            #pragma unroll
            for (int c32 = 0; c32 < 2; c32++) {
                const uint32_t kbyte = (uint32_t)c32 * 64;

                float tacc[2][2][4];
                #pragma unroll
                for (int a = 0; a < 2; a++)
                    #pragma unroll
                    for (int b = 0; b < 2; b++)
                        #pragma unroll
                        for (int c = 0; c < 4; c++) tacc[a][b][c] = 0.f;

                #pragma unroll
                for (int kk = 0; kk < 2; kk++) {
                    uint32_t af[2][4];
                    #pragma unroll
                    for (int mi = 0; mi < 2; mi++) {
                        int row = a_row + mi * 16;
                        ldsm4(af[mi], sb + (uint32_t)((row * SPD2 + a_co) * 2
                                                      + kbyte + kk * 32));
                    }
                    #pragma unroll
                    for (int p = 0; p < 3; p++) {
                        uint32_t ab = sb + (uint32_t)((1 + p) * TSZ * 2);
                        #pragma unroll
                        for (int ni = 0; ni < 2; ni++) {
                            uint32_t bfr[2];
                            int row = b_rb + ni * 8;
                            ldsm2(bfr, ab + (uint32_t)((row * SPD2 + b_co) * 2
                                                       + kbyte + kk * 32));
                            mma16816(tacc[0][ni], af[0], bfr);
                            mma16816(tacc[1][ni], af[1], bfr);
                        }
                    }
                }
                #pragma unroll
                for (int a = 0; a < 2; a++)
                    #pragma unroll
                    for (int b = 0; b < 2; b++)
                        #pragma unroll
                        for (int c = 0; c < 4; c++)
                            master[a][b][c] += tacc[a][b][c];
            }
        }

        __nv_bfloat16* Sout = gS[t & 1];
        #pragma unroll
        for (int mi = 0; mi < 2; mi++)
            #pragma unroll
            for (int ni = 0; ni < 2; ni++)
                #pragma unroll
                for (int h = 0; h < 2; h++)
                    #pragma unroll
                    for (int e = 0; e < 2; e++) {
                        int b = eb[mi][h];
                        int n = en[ni][e];
                        size_t o = ((size_t)b * T_ + t) * H_ + n;
                        float u = __ldcs(&g_U[o]);
                        float mem_prev = memc[mi][ni][h][e];
                        float sp_prev = (mem_prev > 0.5f) ? 1.0f : 0.0f;
                        float y = tanhf(0.5f * master[mi][ni][h * 2 + e] + u);
                        float mem = mem_prev * 0.5f - 0.5f * (1.0f - sp_prev) + y;
                        float sp = (mem > 0.5f) ? 1.0f : 0.0f;
                        __stcs(&out_mems[o], mem);
                        __stcs(&out_spikes[o], sp);
                        Sout[(size_t)b * H_ + n] = __float2bfloat16(sp);
                        memc[mi][ni][h][e] = mem;
                    }

        __threadfence();
        __syncthreads();
        if (tid == 0 && t < T_ - 1) atomicAdd(&gCnt[t][bm], 1u);
    }
}

// ----------------------------------------------------------------------------
extern "C" void kernel_launch(void* const* d_in, const int* in_sizes, int n_in,
                              void* d_out, int out_size)
{
    const float* x        = (const float*)d_in[0];
    const float* W_in     = (const float*)d_in[1];
    const float* Arec     = (const float*)d_in[2];
    const float* bias     = (const float*)d_in[3];
    const float* mem_init = (const float*)d_in[4];

    float* out        = (float*)d_out;
    float* out_mems   = out;
    float* out_spikes = out + (size_t)B_ * T_ * H_;

    cudaFuncSetAttribute(k_frames,
                         cudaFuncAttributeMaxDynamicSharedMemorySize, FR_SMEM_B);

    void* cnt_addr = nullptr;
    cudaGetSymbolAddress(&cnt_addr, gCnt);
    cudaMemsetAsync(cnt_addr, 0, sizeof(unsigned) * T_ * 4);

    { dim3 g(H_ / 32, H_ / 32), b(32, 8); k_split_A<<<g, b>>>(Arec); }
    { dim3 g(H_ / 128, (B_ * T_) / 128); k_input_gemm<<<g, 256>>>(x, W_in, bias); }

    k_frame0<<<(B_ * H_) / 256, 256>>>(mem_init, out_mems, out_spikes);

    dim3 g(H_ / 64, B_ / 64);     // (32, 4) = 128 CTAs, all co-resident
    k_frames<<<g, 256, FR_SMEM_B>>>(out_mems, out_spikes);
}

// round 16
// speedup vs baseline: 1.3997x; 1.1017x over previous
#include <cuda_runtime.h>
#include <cuda_bf16.h>
#include <math.h>
#include <stdint.h>

#define B_    256
#define T_    128
#define NIN   700
#define H_    2048

// ---------------- device scratch ----------------
__device__ float         g_U [(size_t)B_ * T_ * H_];    // 0.5*(x@W+bias), b-major
__device__ __nv_bfloat16 gA0 [(size_t)H_ * H_];         // A^T splits [n][k]
__device__ __nv_bfloat16 gA1 [(size_t)H_ * H_];
__device__ __nv_bfloat16 gA2 [(size_t)H_ * H_];
__device__ __nv_bfloat16 gS  [2][(size_t)B_ * H_];      // spike ping-pong (exact 0/1)
__device__ unsigned      gCnt[T_][4];                   // group barrier counters

// ---------------- asm helpers (sm_80+ portable) ----------------
__device__ __forceinline__ uint32_t smem_u32(const void* p) {
    uint32_t a;
    asm("{ .reg .u64 t; cvta.to.shared.u64 t, %1; cvt.u32.u64 %0, t; }"
        : "=r"(a) : "l"(p));
    return a;
}
__device__ __forceinline__ void cpa16(uint32_t dst, const void* src) {
    asm volatile("cp.async.cg.shared.global [%0], [%1], 16;"
                 :: "r"(dst), "l"(src) : "memory");
}
__device__ __forceinline__ void cpa16_z(uint32_t dst, const void* src, bool v) {
    uint32_t sz = v ? 16u : 0u;
    asm volatile("cp.async.cg.shared.global [%0], [%1], 16, %2;"
                 :: "r"(dst), "l"(src), "r"(sz) : "memory");
}
#define CP_COMMIT() asm volatile("cp.async.commit_group;" ::: "memory")
#define CP_WAIT0()  asm volatile("cp.async.wait_group 0;" ::: "memory")
#define CP_WAIT1()  asm volatile("cp.async.wait_group 1;" ::: "memory")

__device__ __forceinline__ void ldsm4(uint32_t* r, uint32_t a) {
    asm volatile("ldmatrix.sync.aligned.m8n8.x4.shared.b16 {%0,%1,%2,%3}, [%4];"
                 : "=r"(r[0]), "=r"(r[1]), "=r"(r[2]), "=r"(r[3]) : "r"(a));
}
__device__ __forceinline__ void ldsm2(uint32_t* r, uint32_t a) {
    asm volatile("ldmatrix.sync.aligned.m8n8.x2.shared.b16 {%0,%1}, [%2];"
                 : "=r"(r[0]), "=r"(r[1]) : "r"(a));
}
__device__ __forceinline__ void mma16816(float* c, const uint32_t* a,
                                         const uint32_t* b) {
    asm volatile("mma.sync.aligned.m16n8k16.row.col.f32.bf16.bf16.f32 "
                 "{%0,%1,%2,%3}, {%4,%5,%6,%7}, {%8,%9}, {%0,%1,%2,%3};"
                 : "+f"(c[0]), "+f"(c[1]), "+f"(c[2]), "+f"(c[3])
                 : "r"(a[0]), "r"(a[1]), "r"(a[2]), "r"(a[3]),
                   "r"(b[0]), "r"(b[1]));
}
// packed 2-lane IEEE fp32 FMA (Blackwell f32x2; each lane = fma.rn.f32)
__device__ __forceinline__ void ffma2(uint64_t& acc, uint64_t a, uint64_t b) {
    asm("fma.rn.f32x2 %0, %1, %2, %0;" : "+l"(acc) : "l"(a), "l"(b));
}
__device__ __forceinline__ uint64_t pack2(float lo, float hi) {
    uint64_t r;
    asm("mov.b64 %0, {%1, %2};" : "=l"(r) : "f"(lo), "f"(hi));
    return r;
}
__device__ __forceinline__ void unpack2(uint64_t v, float& lo, float& hi) {
    asm("mov.b64 {%0, %1}, %2;" : "=f"(lo), "=f"(hi) : "l"(v));
}

// ---------------- bf16 3-way exact split ----------------
__device__ __forceinline__ void split3(float v, __nv_bfloat16& b0,
                                       __nv_bfloat16& b1, __nv_bfloat16& b2) {
    b0 = __float2bfloat16(v);
    float f0 = __bfloat162float(b0);
    b1 = __float2bfloat16(v - f0);
    float f1 = __bfloat162float(b1);
    b2 = __float2bfloat16(v - f0 - f1);
}

__global__ void k_split_A(const float* __restrict__ A) {
    __shared__ float tile[32][33];
    int tx = threadIdx.x, ty = threadIdx.y;
    int kbase = blockIdx.y * 32, nbase = blockIdx.x * 32;
    #pragma unroll
    for (int i = 0; i < 32; i += 8)
        tile[ty + i][tx] = A[(size_t)(kbase + ty + i) * H_ + nbase + tx];
    __syncthreads();
    #pragma unroll
    for (int i = 0; i < 32; i += 8) {
        float v = tile[tx][ty + i];
        size_t o = (size_t)(nbase + ty + i) * H_ + kbase + tx;
        __nv_bfloat16 b0, b1, b2; split3(v, b0, b1, b2);
        gA0[o] = b0; gA1[o] = b1; gA2[o] = b2;
    }
}

// ------- input GEMM: fp32 FFMA2, ascending-k order (verbatim round 14) -----
__global__ void __launch_bounds__(256) k_input_gemm(
    const float* __restrict__ X, const float* __restrict__ W,
    const float* __restrict__ bias)
{
    constexpr int K = NIN, N = H_;
    constexpr int BM = 128, BN = 128, BK = 16, TM = 8, TN = 8;
    __shared__ __align__(16) float As[2][BM][BK];
    __shared__ __align__(16) float Bs[2][BK][BN];

    const int tid = threadIdx.x;
    const int bm = blockIdx.y, bn = blockIdx.x;
    const int tRow = (tid >> 4) << 3, tCol = (tid & 15) << 3;
    const int m0g = bm * BM, n0g = bn * BN;

    auto load_stage = [&](int buf, int k0) {
        #pragma unroll
        for (int h = 0; h < 2; h++) {
            int c = tid + h * 256;
            int ar = c >> 2, aj = (c & 3) * 4;
            cpa16_z(smem_u32(&As[buf][ar][aj]),
                    X + (size_t)(m0g + ar) * K + k0 + aj, (k0 + aj) < K);
            int brw = c >> 5, bc = (c & 31) * 4;
            cpa16_z(smem_u32(&Bs[buf][brw][bc]),
                    W + (size_t)(k0 + brw) * N + n0g + bc, (k0 + brw) < K);
        }
    };

    uint64_t accP[TM][TN / 2];
    #pragma unroll
    for (int i = 0; i < TM; i++)
        #pragma unroll
        for (int j = 0; j < TN / 2; j++) accP[i][j] = pack2(0.f, 0.f);

    constexpr int NS = (K + BK - 1) / BK;   // 44
    load_stage(0, 0); CP_COMMIT();

    for (int s = 0; s < NS; s++) {
        int buf = s & 1;
        __syncthreads();
        if (s + 1 < NS) { load_stage(buf ^ 1, (s + 1) * BK); CP_COMMIT(); CP_WAIT1(); }
        else CP_WAIT0();
        __syncthreads();

        #pragma unroll
        for (int k = 0; k < BK; k++) {
            uint64_t aP[TM];
            #pragma unroll
            for (int i = 0; i < TM; i++) {
                float a = As[buf][tRow + i][k];
                aP[i] = pack2(a, a);
            }
            float4 b0 = *(const float4*)&Bs[buf][k][tCol];
            float4 b1 = *(const float4*)&Bs[buf][k][tCol + 4];
            uint64_t bP[TN / 2];
            bP[0] = pack2(b0.x, b0.y);
            bP[1] = pack2(b0.z, b0.w);
            bP[2] = pack2(b1.x, b1.y);
            bP[3] = pack2(b1.z, b1.w);
            #pragma unroll
            for (int i = 0; i < TM; i++)
                #pragma unroll
                for (int j = 0; j < TN / 2; j++)
                    ffma2(accP[i][j], aP[i], bP[j]);
        }
    }

    const int m0 = m0g + tRow, n0 = n0g + tCol;
    #pragma unroll
    for (int i = 0; i < TM; i++) {
        size_t row = (size_t)(m0 + i) * N;
        #pragma unroll
        for (int j = 0; j < TN / 2; j++) {
            float lo, hi;
            unpack2(accP[i][j], lo, hi);
            g_U[row + n0 + 2 * j + 0] = 0.5f * (lo + bias[n0 + 2 * j + 0]);
            g_U[row + n0 + 2 * j + 1] = 0.5f * (hi + bias[n0 + 2 * j + 1]);
        }
    }
}

// ---------------- frame 0 (spike0 = 0 -> r = 0) ----------------
__global__ void k_frame0(const float* __restrict__ mem_init,
                         float* __restrict__ out_mems,
                         float* __restrict__ out_spikes)
{
    size_t idx = (size_t)blockIdx.x * 256 + threadIdx.x;
    int b = (int)(idx / H_), n = (int)(idx % H_);
    size_t o = ((size_t)b * T_) * H_ + n;
    float u = g_U[o];
    float y = tanhf(u);
    float mem = mem_init[idx] * 0.5f - 0.5f * (1.0f - 0.0f) + y;
    float sp = (mem > 0.5f) ? 1.0f : 0.0f;
    out_mems[o] = mem;
    out_spikes[o] = sp;
    gS[0][idx] = __float2bfloat16(sp);
}

// ==== persistent frames: interleaved-chunk mainloop (8 mma chains/warp) ====
// Per-element accumulation order BIT-IDENTICAL to rounds 6..14: each BK=32
// chunk's chain is kk0p0,kk0p1,kk0p2,kk1p0,kk1p1,kk1p2 from a zero tacc; the
// two chunks' folds into master stay in c32=0-then-c32=1 order. Interleaving
// only changes instruction scheduling, not any element's FP sequence.
#define SPD2 72
#define TSZ  (64 * SPD2)
#define STG  (4 * TSZ)
#define FR_SMEM_B (3 * STG * 2)          // 110592 B

__global__ void __launch_bounds__(256)
k_frames(float* __restrict__ out_mems, float* __restrict__ out_spikes)
{
    extern __shared__ __align__(16) __nv_bfloat16 smf[];
    const int tid = threadIdx.x;
    const int lane = tid & 31, w = tid >> 5;
    const int wm = w & 1, wn = w >> 1;               // warp tile 32(m) x 16(n)
    const int l15 = lane & 15;
    const int n0 = blockIdx.x * 64, m0 = blockIdx.y * 64;
    const int bm = blockIdx.y;

    const __nv_bfloat16* Ap[3] = { gA0 + (size_t)n0 * H_,
                                   gA1 + (size_t)n0 * H_,
                                   gA2 + (size_t)n0 * H_ };

    const int gq = lane >> 2, tq = lane & 3;
    int eb[2][2], en[2][2];
    #pragma unroll
    for (int mi = 0; mi < 2; mi++)
        #pragma unroll
        for (int h = 0; h < 2; h++)
            eb[mi][h] = m0 + wm * 32 + mi * 16 + gq + h * 8;
    #pragma unroll
    for (int ni = 0; ni < 2; ni++)
        #pragma unroll
        for (int e = 0; e < 2; e++)
            en[ni][e] = n0 + wn * 16 + ni * 8 + tq * 2 + e;

    float memc[2][2][2][2];
    #pragma unroll
    for (int mi = 0; mi < 2; mi++)
        #pragma unroll
        for (int ni = 0; ni < 2; ni++)
            #pragma unroll
            for (int h = 0; h < 2; h++)
                #pragma unroll
                for (int e = 0; e < 2; e++)
                    memc[mi][ni][h][e] =
                        out_mems[((size_t)eb[mi][h] * T_) * H_ + en[ni][e]];

    const int a_row = wm * 32 + l15;
    const int b_rb  = wn * 16 + (l15 & 7);
    const int a_co  = (lane >> 4) * 8;
    const int b_co  = ((l15 >> 3) & 1) * 8;

    for (int t = 1; t < T_; t++) {
        if (t >= 2) {
            if (tid == 0)
                while (atomicAdd(&gCnt[t - 1][bm], 0u) < 32u) __nanosleep(32);
            __syncthreads();
        }

        const __nv_bfloat16* Sg = gS[(t + 1) & 1];

        // prefetch epilogue g_U values (fixed before launch; overlaps mainloop)
        float uc[2][2][2][2];
        #pragma unroll
        for (int mi = 0; mi < 2; mi++)
            #pragma unroll
            for (int ni = 0; ni < 2; ni++)
                #pragma unroll
                for (int h = 0; h < 2; h++)
                    #pragma unroll
                    for (int e = 0; e < 2; e++)
                        uc[mi][ni][h][e] = __ldcs(
                            &g_U[((size_t)eb[mi][h] * T_ + t) * H_ + en[ni][e]]);

        auto load_stage = [&](int buf, int k0) {
            __nv_bfloat16* st = smf + (size_t)buf * STG;
            #pragma unroll
            for (int i = 0; i < 8; i++) {
                int c = tid + i * 256;
                int tile = c >> 9;
                int r = (c >> 3) & 63;
                int j = (c & 7) * 8;
                const __nv_bfloat16* src = (tile == 0)
                    ? Sg + (size_t)(m0 + r) * H_ + k0 + j
                    : Ap[tile - 1] + (size_t)r * H_ + k0 + j;
                cpa16(smem_u32(st + tile * TSZ + r * SPD2 + j), src);
            }
        };

        float master[2][2][4];
        #pragma unroll
        for (int a = 0; a < 2; a++)
            #pragma unroll
            for (int b = 0; b < 2; b++)
                #pragma unroll
                for (int c = 0; c < 4; c++) master[a][b][c] = 0.f;

        load_stage(0, 0);  CP_COMMIT();
        load_stage(1, 64); CP_COMMIT();

        constexpr int NS = H_ / 64;     // 32 stages, BK=64 (2 x BK=32 chunks)
        for (int s = 0; s < NS; s++) {
            int buf = s % 3;
            CP_WAIT1();
            __syncthreads();
            if (s + 2 < NS) load_stage((s + 2) % 3, (s + 2) * 64);
            CP_COMMIT();

            uint32_t sb = smem_u32(smf + (size_t)buf * STG);

            // both BK=32 chunks interleaved: 8 independent mma chains
            float tacc[2][2][2][4];     // [c32][a][ni][4]
            #pragma unroll
            for (int q = 0; q < 2; q++)
                #pragma unroll
                for (int a = 0; a < 2; a++)
                    #pragma unroll
                    for (int b = 0; b < 2; b++)
                        #pragma unroll
                        for (int c = 0; c < 4; c++) tacc[q][a][b][c] = 0.f;

            #pragma unroll
            for (int kk = 0; kk < 2; kk++) {
                uint32_t af[2][2][4];   // [c32][mi]
                #pragma unroll
                for (int c32 = 0; c32 < 2; c32++)
                    #pragma unroll
                    for (int mi = 0; mi < 2; mi++) {
                        int row = a_row + mi * 16;
                        ldsm4(af[c32][mi],
                              sb + (uint32_t)((row * SPD2 + a_co) * 2
                                              + c32 * 64 + kk * 32));
                    }
                #pragma unroll
                for (int p = 0; p < 3; p++) {
                    uint32_t ab = sb + (uint32_t)((1 + p) * TSZ * 2);
                    #pragma unroll
                    for (int c32 = 0; c32 < 2; c32++)
                        #pragma unroll
                        for (int ni = 0; ni < 2; ni++) {
                            uint32_t bfr[2];
                            int row = b_rb + ni * 8;
                            ldsm2(bfr, ab + (uint32_t)((row * SPD2 + b_co) * 2
                                                       + c32 * 64 + kk * 32));
                            mma16816(tacc[c32][0][ni], af[c32][0], bfr);
                            mma16816(tacc[c32][1][ni], af[c32][1], bfr);
                        }
                }
            }
            // folds in original chunk order: c32=0 then c32=1
            #pragma unroll
            for (int q = 0; q < 2; q++)
                #pragma unroll
                for (int a = 0; a < 2; a++)
                    #pragma unroll
                    for (int b = 0; b < 2; b++)
                        #pragma unroll
                        for (int c = 0; c < 4; c++)
                            master[a][b][c] += tacc[q][a][b][c];
        }

        __nv_bfloat16* Sout = gS[t & 1];
        #pragma unroll
        for (int mi = 0; mi < 2; mi++)
            #pragma unroll
            for (int ni = 0; ni < 2; ni++)
                #pragma unroll
                for (int h = 0; h < 2; h++)
                    #pragma unroll
                    for (int e = 0; e < 2; e++) {
                        int b = eb[mi][h];
                        int n = en[ni][e];
                        size_t o = ((size_t)b * T_ + t) * H_ + n;
                        float u = uc[mi][ni][h][e];
                        float mem_prev = memc[mi][ni][h][e];
                        float sp_prev = (mem_prev > 0.5f) ? 1.0f : 0.0f;
                        float y = tanhf(0.5f * master[mi][ni][h * 2 + e] + u);
                        float mem = mem_prev * 0.5f - 0.5f * (1.0f - sp_prev) + y;
                        float sp = (mem > 0.5f) ? 1.0f : 0.0f;
                        __stcs(&out_mems[o], mem);
                        __stcs(&out_spikes[o], sp);
                        Sout[(size_t)b * H_ + n] = __float2bfloat16(sp);
                        memc[mi][ni][h][e] = mem;
                    }

        __threadfence();
        __syncthreads();
        if (tid == 0 && t < T_ - 1) atomicAdd(&gCnt[t][bm], 1u);
    }
}

// ----------------------------------------------------------------------------
extern "C" void kernel_launch(void* const* d_in, const int* in_sizes, int n_in,
                              void* d_out, int out_size)
{
    const float* x        = (const float*)d_in[0];
    const float* W_in     = (const float*)d_in[1];
    const float* Arec     = (const float*)d_in[2];
    const float* bias     = (const float*)d_in[3];
    const float* mem_init = (const float*)d_in[4];

    float* out        = (float*)d_out;
    float* out_mems   = out;
    float* out_spikes = out + (size_t)B_ * T_ * H_;

    cudaFuncSetAttribute(k_frames,
                         cudaFuncAttributeMaxDynamicSharedMemorySize, FR_SMEM_B);

    void* cnt_addr = nullptr;
    cudaGetSymbolAddress(&cnt_addr, gCnt);
    cudaMemsetAsync(cnt_addr, 0, sizeof(unsigned) * T_ * 4);

    { dim3 g(H_ / 32, H_ / 32), b(32, 8); k_split_A<<<g, b>>>(Arec); }
    { dim3 g(H_ / 128, (B_ * T_) / 128); k_input_gemm<<<g, 256>>>(x, W_in, bias); }

    k_frame0<<<(B_ * H_) / 256, 256>>>(mem_init, out_mems, out_spikes);

    dim3 g(H_ / 64, B_ / 64);     // (32, 4) = 128 CTAs, all co-resident
    k_frames<<<g, 256, FR_SMEM_B>>>(out_mems, out_spikes);
}